// round 5
// baseline (speedup 1.0000x reference)
#include <cuda_runtime.h>
#include <cuda_bf16.h>
#include <cstdint>
#include <math.h>

#define DI __device__ __forceinline__
typedef unsigned U32;

// T=512, B=64, H=1024, 3H=3072, M=T*B=32768
__device__ float          g_gi[100663296];        // [32768][3072]
__device__ __nv_bfloat16  g_whh[3145728];         // W_h^T hi [3072][1024]
__device__ __nv_bfloat16  g_whl[3145728];         // W_h^T lo
__device__ float          g_hf [2][65536];        // masked h fp32 [par][64][1024]
__device__ __nv_bfloat16  g_hhi[2][65536];
__device__ __nv_bfloat16  g_hlo[2][65536];
__device__ int            g_bar;
__device__ int            g_rmode;                // 0=int32 1=uint8 2=float32

DI void mma16816(float d[4], const U32 a[4], const U32 b[2]) {
    asm volatile(
        "mma.sync.aligned.m16n8k16.row.col.f32.bf16.bf16.f32 "
        "{%0,%1,%2,%3},{%4,%5,%6,%7},{%8,%9},{%0,%1,%2,%3};\n"
        : "+f"(d[0]), "+f"(d[1]), "+f"(d[2]), "+f"(d[3])
        : "r"(a[0]), "r"(a[1]), "r"(a[2]), "r"(a[3]), "r"(b[0]), "r"(b[1]));
}
DI __nv_bfloat16 bhi(float x) { return __float2bfloat16(x); }
DI __nv_bfloat16 blo(float x, __nv_bfloat16 h) { return __float2bfloat16(x - __bfloat162float(h)); }

// -------- init: zero h buffers, reset barrier, probe resets dtype --------
__global__ void initk(const unsigned char* __restrict__ rs) {
    int i = blockIdx.x * blockDim.x + threadIdx.x;
    int nt = gridDim.x * blockDim.x;
    if (i == 0) {
        g_bar = 0;
        int mode = 0;
        for (int b = 0; b < 16384; ++b) {
            if ((b & 3) == 3 && rs[b] == 0x3F) { mode = 2; break; }
            if ((b & 3) != 0 && rs[b] != 0 && mode == 0) mode = 1;
        }
        g_rmode = mode;
    }
    for (int k = i; k < 2 * 65536; k += nt) {
        (&g_hf[0][0])[k] = 0.0f;
        (&g_hhi[0][0])[k] = __float2bfloat16(0.0f);
        (&g_hlo[0][0])[k] = __float2bfloat16(0.0f);
    }
}

// -------- W_h fp32 [1024][3072] -> transposed split-bf16 [3072][1024] --------
__global__ void convw(const float* __restrict__ Wh) {
    int idx = blockIdx.x * 256 + threadIdx.x;
    if (idx >= 3072 * 1024) return;
    int k = idx / 3072, n = idx % 3072;
    float x = Wh[idx];
    __nv_bfloat16 h = bhi(x);
    g_whh[(size_t)n * 1024 + k] = h;
    g_whl[(size_t)n * 1024 + k] = blo(x, h);
}

// -------- phase 1: gi = ins @ W_i + b_i, split-bf16 mma, 128x128x32 tiles ----
__global__ void __launch_bounds__(256, 1)
phase1(const float* __restrict__ A, const float* __restrict__ B, const float* __restrict__ bias) {
    __shared__ __nv_bfloat16 Ah[128][40], Al[128][40], Bh[128][40], Bl[128][40];
    const int tid = threadIdx.x, warp = tid >> 5, lane = tid & 31;
    const int g = lane >> 2, t = lane & 3;
    const int m0 = blockIdx.y * 128, n0 = blockIdx.x * 128;
    const int wm = (warp & 3) * 32, wn = (warp >> 2) * 64;
    float acc[2][8][4];
#pragma unroll
    for (int mi = 0; mi < 2; ++mi)
#pragma unroll
        for (int ni = 0; ni < 8; ++ni)
#pragma unroll
            for (int e = 0; e < 4; ++e) acc[mi][ni][e] = 0.f;

    for (int k0 = 0; k0 < 1024; k0 += 32) {
        {   // A tile 128x32: 2 threads/row, 16 floats each
            int row = tid >> 1, col = (tid & 1) * 16;
            const float* p = A + (size_t)(m0 + row) * 1024 + k0 + col;
#pragma unroll
            for (int v = 0; v < 4; ++v) {
                float4 x = *(const float4*)(p + v * 4);
                float xs[4] = {x.x, x.y, x.z, x.w};
#pragma unroll
                for (int c = 0; c < 4; ++c) {
                    __nv_bfloat16 h = bhi(xs[c]);
                    Ah[row][col + v * 4 + c] = h;
                    Al[row][col + v * 4 + c] = blo(xs[c], h);
                }
            }
        }
        {   // B tile 32x128 -> transposed smem [n][k]
            int kr = tid >> 3, nb = (tid & 7) * 16;
            const float* p = B + (size_t)(k0 + kr) * 3072 + n0 + nb;
#pragma unroll
            for (int v = 0; v < 4; ++v) {
                float4 x = *(const float4*)(p + v * 4);
                float xs[4] = {x.x, x.y, x.z, x.w};
#pragma unroll
                for (int c = 0; c < 4; ++c) {
                    __nv_bfloat16 h = bhi(xs[c]);
                    Bh[nb + v * 4 + c][kr] = h;
                    Bl[nb + v * 4 + c][kr] = blo(xs[c], h);
                }
            }
        }
        __syncthreads();
#pragma unroll
        for (int k16 = 0; k16 < 2; ++k16) {
            int kk = k16 * 16 + 2 * t;
            U32 ah[2][4], al[2][4];
#pragma unroll
            for (int mi = 0; mi < 2; ++mi) {
                int r = wm + mi * 16 + g;
                ah[mi][0] = *(const U32*)&Ah[r][kk];     ah[mi][1] = *(const U32*)&Ah[r + 8][kk];
                ah[mi][2] = *(const U32*)&Ah[r][kk + 8]; ah[mi][3] = *(const U32*)&Ah[r + 8][kk + 8];
                al[mi][0] = *(const U32*)&Al[r][kk];     al[mi][1] = *(const U32*)&Al[r + 8][kk];
                al[mi][2] = *(const U32*)&Al[r][kk + 8]; al[mi][3] = *(const U32*)&Al[r + 8][kk + 8];
            }
#pragma unroll
            for (int ni = 0; ni < 8; ++ni) {
                int nn = wn + ni * 8 + g;
                U32 bh[2] = {*(const U32*)&Bh[nn][kk], *(const U32*)&Bh[nn][kk + 8]};
                U32 bl[2] = {*(const U32*)&Bl[nn][kk], *(const U32*)&Bl[nn][kk + 8]};
#pragma unroll
                for (int mi = 0; mi < 2; ++mi) {
                    mma16816(acc[mi][ni], ah[mi], bh);
                    mma16816(acc[mi][ni], ah[mi], bl);
                    mma16816(acc[mi][ni], al[mi], bh);
                }
            }
        }
        __syncthreads();
    }
#pragma unroll
    for (int mi = 0; mi < 2; ++mi)
#pragma unroll
        for (int ni = 0; ni < 8; ++ni)
#pragma unroll
            for (int e = 0; e < 4; ++e) {
                int row = m0 + wm + mi * 16 + g + ((e & 2) ? 8 : 0);
                int col = n0 + wn + ni * 8 + 2 * t + (e & 1);
                g_gi[(size_t)row * 3072 + col] = acc[mi][ni][e] + bias[col];
            }
}

// -------- phase 2: persistent recurrence, 128 CTAs, W_h slice in smem -------
#define P2_CTAS 128
__global__ void __launch_bounds__(256, 1)
phase2(const unsigned char* __restrict__ rs, const float* __restrict__ bhn,
       float* __restrict__ out) {
    extern __shared__ __align__(16) char smraw[];
    __nv_bfloat16* Wh = (__nv_bfloat16*)smraw;      // [24][1032]
    __nv_bfloat16* Wl = Wh + 24 * 1032;
    float* red = (float*)(Wl + 24 * 1032);          // [64][24]

    const int tid = threadIdx.x, warp = tid >> 5, lane = tid & 31;
    const int g = lane >> 2, t = lane & 3;
    const int j0 = blockIdx.x * 8;
    const int mw = warp >> 1, ks = warp & 1;        // m-tile, K-split half
    const int rmode = g_rmode;

    // stage this CTA's W_h slice (24 gh-columns) into smem, kept all 512 steps
    for (int i = tid; i < 3072; i += 256) {         // 24 rows x 128 uint4
        int nl = i >> 7, o8 = (i & 127) << 3;
        size_t ng = (size_t)((nl >> 3) * 1024 + j0 + (nl & 7)) * 1024 + o8;
        *(uint4*)&Wh[nl * 1032 + o8] = *(const uint4*)&g_whh[ng];
        *(uint4*)&Wl[nl * 1032 + o8] = *(const uint4*)&g_whl[ng];
    }
    __syncthreads();

    for (int s = 0; s < 512; ++s) {
        const int par = s & 1;
        const __nv_bfloat16* Ahg = g_hhi[par];
        const __nv_bfloat16* Alg = g_hlo[par];
        const int r0 = mw * 16 + g;
        float acc[3][4];
#pragma unroll
        for (int q = 0; q < 3; ++q)
#pragma unroll
            for (int e = 0; e < 4; ++e) acc[q][e] = 0.f;

#pragma unroll 2
        for (int k16 = 0; k16 < 32; ++k16) {
            int kk = ks * 512 + k16 * 16 + 2 * t;
            U32 ah[4], al[4];
            ah[0] = *(const U32*)&Ahg[r0 * 1024 + kk];
            ah[1] = *(const U32*)&Ahg[(r0 + 8) * 1024 + kk];
            ah[2] = *(const U32*)&Ahg[r0 * 1024 + kk + 8];
            ah[3] = *(const U32*)&Ahg[(r0 + 8) * 1024 + kk + 8];
            al[0] = *(const U32*)&Alg[r0 * 1024 + kk];
            al[1] = *(const U32*)&Alg[(r0 + 8) * 1024 + kk];
            al[2] = *(const U32*)&Alg[r0 * 1024 + kk + 8];
            al[3] = *(const U32*)&Alg[(r0 + 8) * 1024 + kk + 8];
#pragma unroll
            for (int gate = 0; gate < 3; ++gate) {
                int nl = gate * 8 + g;
                U32 bh[2] = {*(const U32*)&Wh[nl * 1032 + kk], *(const U32*)&Wh[nl * 1032 + kk + 8]};
                U32 bl[2] = {*(const U32*)&Wl[nl * 1032 + kk], *(const U32*)&Wl[nl * 1032 + kk + 8]};
                mma16816(acc[gate], ah, bh);
                mma16816(acc[gate], ah, bl);
                mma16816(acc[gate], al, bh);
            }
        }
        if (ks == 1) {
#pragma unroll
            for (int gate = 0; gate < 3; ++gate)
#pragma unroll
                for (int e = 0; e < 4; ++e) {
                    int row = mw * 16 + g + ((e & 2) ? 8 : 0);
                    red[row * 24 + gate * 8 + 2 * t + (e & 1)] = acc[gate][e];
                }
        }
        __syncthreads();
        if (ks == 0) {
#pragma unroll
            for (int e = 0; e < 4; ++e) {
                int row = mw * 16 + g + ((e & 2) ? 8 : 0);
                int jc = 2 * t + (e & 1);
                int j = j0 + jc;
                float ar = acc[0][e] + red[row * 24 + jc];
                float az = acc[1][e] + red[row * 24 + 8 + jc];
                float an = acc[2][e] + red[row * 24 + 16 + jc];
                size_t gb = ((size_t)s * 64 + row) * 3072 + j;
                float ir = g_gi[gb], iz = g_gi[gb + 1024], inn = g_gi[gb + 2048];
                float hp = g_hf[par][row * 1024 + j];
                float r = 1.f / (1.f + expf(-(ir + ar)));
                float z = 1.f / (1.f + expf(-(iz + az)));
                float n = tanhf(inn + r * (an + bhn[j]));
                float hn = (1.f - z) * n + z * hp;
                out[((size_t)s * 64 + row) * 1024 + j] = hn;
                if (s + 1 < 512) {
                    int ri = (s + 1) * 64 + row;
                    int rf = (rmode == 1) ? rs[ri] : (rmode == 0) ? rs[ri * 4] : rs[ri * 4 + 3];
                    float hm = rf ? 0.f : hn;
                    g_hf[1 - par][row * 1024 + j] = hm;
                    __nv_bfloat16 h = bhi(hm);
                    g_hhi[1 - par][row * 1024 + j] = h;
                    g_hlo[1 - par][row * 1024 + j] = blo(hm, h);
                }
            }
        }
        __syncthreads();
        if (tid == 0) {
            __threadfence();
            atomicAdd(&g_bar, 1);
            int tgt = P2_CTAS * (s + 1);
            while (*(volatile int*)&g_bar < tgt) __nanosleep(32);
            __threadfence();
        }
        __syncthreads();
    }
}

extern "C" void kernel_launch(void* const* d_in, const int* in_sizes, int n_in,
                              void* d_out, int out_size) {
    const float*         ins  = (const float*)d_in[0];
    const unsigned char* rs   = (const unsigned char*)d_in[1];
    const float*         Wi   = (const float*)d_in[2];
    const float*         bi   = (const float*)d_in[3];
    const float*         Whm  = (const float*)d_in[4];
    const float*         bhn  = (const float*)d_in[5];
    float*               out  = (float*)d_out;
    (void)in_sizes; (void)n_in; (void)out_size;

    int smem2 = (24 * 1032 * 2 * 2) + 64 * 24 * 4;   // 105216 B
    cudaFuncSetAttribute(phase2, cudaFuncAttributeMaxDynamicSharedMemorySize, smem2);

    initk<<<64, 256>>>(rs);
    convw<<<(3072 * 1024 + 255) / 256, 256>>>(Whm);
    phase1<<<dim3(24, 256), 256>>>(ins, Wi, bi);
    phase2<<<P2_CTAS, 256, smem2>>>(rs, bhn, out);
}

// round 8
// speedup vs baseline: 1.0693x; 1.0693x over previous
#include <cuda_runtime.h>
#include <cuda_bf16.h>
#include <cstdint>
#include <math.h>

#define DI __device__ __forceinline__
typedef unsigned U32;

// T=512, B=64, H=1024, 3H=3072, M=T*B=32768
__device__ float          g_gi[100663296];        // [32768][3072]
__device__ __nv_bfloat16  g_whh[3145728];         // W_h^T hi [3072][1024]
__device__ __nv_bfloat16  g_whl[3145728];         // W_h^T lo
__device__ float          g_hf [2][65536];        // masked h fp32 [par][64][1024]
__device__ __nv_bfloat16  g_hhi[2][65536];
__device__ __nv_bfloat16  g_hlo[2][65536];
__device__ float          g_rmask[32768];         // [512][64]: reset?0:1
__device__ int            g_bar;
__device__ int            g_rmode;                // 0=int32 1=uint8 2=float32

DI void mma16816(float d[4], const U32 a[4], const U32 b[2]) {
    asm volatile(
        "mma.sync.aligned.m16n8k16.row.col.f32.bf16.bf16.f32 "
        "{%0,%1,%2,%3},{%4,%5,%6,%7},{%8,%9},{%0,%1,%2,%3};\n"
        : "+f"(d[0]), "+f"(d[1]), "+f"(d[2]), "+f"(d[3])
        : "r"(a[0]), "r"(a[1]), "r"(a[2]), "r"(a[3]), "r"(b[0]), "r"(b[1]));
}
DI __nv_bfloat16 bhi(float x) { return __float2bfloat16(x); }
DI __nv_bfloat16 blo(float x, __nv_bfloat16 h) { return __float2bfloat16(x - __bfloat162float(h)); }

DI void cpa16(void* dst, const void* src) {
    unsigned d = (unsigned)__cvta_generic_to_shared(dst);
    asm volatile("cp.async.cg.shared.global [%0], [%1], 16;\n" :: "r"(d), "l"(src));
}
DI void cpcommit() { asm volatile("cp.async.commit_group;\n" ::: "memory"); }
template<int N> DI void cpwait() { asm volatile("cp.async.wait_group %0;\n" :: "n"(N) : "memory"); }
DI float tanh_fast(float x) { float y; asm("tanh.approx.f32 %0, %1;\n" : "=f"(y) : "f"(x)); return y; }

// -------- init: zero h buffers, reset barrier, probe resets dtype --------
__global__ void initk(const unsigned char* __restrict__ rs) {
    int i = blockIdx.x * blockDim.x + threadIdx.x;
    int nt = gridDim.x * blockDim.x;
    if (i == 0) {
        g_bar = 0;
        int mode = 0;
        for (int b = 0; b < 16384; ++b) {
            if ((b & 3) == 3 && rs[b] == 0x3F) { mode = 2; break; }
            if ((b & 3) != 0 && rs[b] != 0 && mode == 0) mode = 1;
        }
        g_rmode = mode;
    }
    for (int k = i; k < 2 * 65536; k += nt) {
        (&g_hf[0][0])[k] = 0.0f;
        (&g_hhi[0][0])[k] = __float2bfloat16(0.0f);
        (&g_hlo[0][0])[k] = __float2bfloat16(0.0f);
    }
}

// -------- resets -> float mask (after rmode known) --------
__global__ void rmaskk(const unsigned char* __restrict__ rs) {
    int i = blockIdx.x * blockDim.x + threadIdx.x;
    if (i >= 32768) return;
    int mode = g_rmode;
    int v = (mode == 1) ? rs[i] : (mode == 0) ? rs[i * 4] : rs[i * 4 + 3];
    g_rmask[i] = v ? 0.f : 1.f;
}

// -------- W_h fp32 [1024][3072] -> transposed split-bf16 [3072][1024] --------
__global__ void convw(const float* __restrict__ Wh) {
    int idx = blockIdx.x * 256 + threadIdx.x;
    if (idx >= 3072 * 1024) return;
    int k = idx / 3072, n = idx % 3072;
    float x = Wh[idx];
    __nv_bfloat16 h = bhi(x);
    g_whh[(size_t)n * 1024 + k] = h;
    g_whl[(size_t)n * 1024 + k] = blo(x, h);
}

// -------- phase 1: gi = ins @ W_i + b_i, split-bf16 mma, 128x128x32 tiles ----
__global__ void __launch_bounds__(256, 1)
phase1(const float* __restrict__ A, const float* __restrict__ B, const float* __restrict__ bias) {
    __shared__ __nv_bfloat16 Ah[128][40], Al[128][40], Bh[128][40], Bl[128][40];
    const int tid = threadIdx.x, warp = tid >> 5, lane = tid & 31;
    const int g = lane >> 2, t = lane & 3;
    const int m0 = blockIdx.y * 128, n0 = blockIdx.x * 128;
    const int wm = (warp & 3) * 32, wn = (warp >> 2) * 64;
    float acc[2][8][4];
#pragma unroll
    for (int mi = 0; mi < 2; ++mi)
#pragma unroll
        for (int ni = 0; ni < 8; ++ni)
#pragma unroll
            for (int e = 0; e < 4; ++e) acc[mi][ni][e] = 0.f;

    for (int k0 = 0; k0 < 1024; k0 += 32) {
        {   // A tile 128x32
            int row = tid >> 1, col = (tid & 1) * 16;
            const float* p = A + (size_t)(m0 + row) * 1024 + k0 + col;
#pragma unroll
            for (int v = 0; v < 4; ++v) {
                float4 x = *(const float4*)(p + v * 4);
                float xs[4] = {x.x, x.y, x.z, x.w};
#pragma unroll
                for (int c = 0; c < 4; ++c) {
                    __nv_bfloat16 h = bhi(xs[c]);
                    Ah[row][col + v * 4 + c] = h;
                    Al[row][col + v * 4 + c] = blo(xs[c], h);
                }
            }
        }
        {   // B tile 32x128 -> transposed smem [n][k]
            int kr = tid >> 3, nb = (tid & 7) * 16;
            const float* p = B + (size_t)(k0 + kr) * 3072 + n0 + nb;
#pragma unroll
            for (int v = 0; v < 4; ++v) {
                float4 x = *(const float4*)(p + v * 4);
                float xs[4] = {x.x, x.y, x.z, x.w};
#pragma unroll
                for (int c = 0; c < 4; ++c) {
                    __nv_bfloat16 h = bhi(xs[c]);
                    Bh[nb + v * 4 + c][kr] = h;
                    Bl[nb + v * 4 + c][kr] = blo(xs[c], h);
                }
            }
        }
        __syncthreads();
#pragma unroll
        for (int k16 = 0; k16 < 2; ++k16) {
            int kk = k16 * 16 + 2 * t;
            U32 ah[2][4], al[2][4];
#pragma unroll
            for (int mi = 0; mi < 2; ++mi) {
                int r = wm + mi * 16 + g;
                ah[mi][0] = *(const U32*)&Ah[r][kk];     ah[mi][1] = *(const U32*)&Ah[r + 8][kk];
                ah[mi][2] = *(const U32*)&Ah[r][kk + 8]; ah[mi][3] = *(const U32*)&Ah[r + 8][kk + 8];
                al[mi][0] = *(const U32*)&Al[r][kk];     al[mi][1] = *(const U32*)&Al[r + 8][kk];
                al[mi][2] = *(const U32*)&Al[r][kk + 8]; al[mi][3] = *(const U32*)&Al[r + 8][kk + 8];
            }
#pragma unroll
            for (int ni = 0; ni < 8; ++ni) {
                int nn = wn + ni * 8 + g;
                U32 bh[2] = {*(const U32*)&Bh[nn][kk], *(const U32*)&Bh[nn][kk + 8]};
                U32 bl[2] = {*(const U32*)&Bl[nn][kk], *(const U32*)&Bl[nn][kk + 8]};
#pragma unroll
                for (int mi = 0; mi < 2; ++mi) {
                    mma16816(acc[mi][ni], ah[mi], bh);
                    mma16816(acc[mi][ni], ah[mi], bl);
                    mma16816(acc[mi][ni], al[mi], bh);
                }
            }
        }
        __syncthreads();
    }
#pragma unroll
    for (int mi = 0; mi < 2; ++mi)
#pragma unroll
        for (int ni = 0; ni < 8; ++ni)
#pragma unroll
            for (int e = 0; e < 4; ++e) {
                int row = m0 + wm + mi * 16 + g + ((e & 2) ? 8 : 0);
                int col = n0 + wn + ni * 8 + 2 * t + (e & 1);
                g_gi[(size_t)row * 3072 + col] = acc[mi][ni][e] + bias[col];
            }
}

// -------- phase 2: persistent recurrence, cp.async pipelined h staging -------
#define P2_CTAS 128
// smem layout (bytes):
//   Wh  [24][1032] bf16           @      0   (49536)
//   Wl  [24][1032] bf16           @  49536   (49536)
//   hbuf 3 x { hi[64][136], lo[64][136] } bf16  @ 99072  (104448)
//   red [3][64][24] f32           @ 203520  (18432)
//   gi  [64][24] f32              @ 221952  (6144)
//   hp  [64][8]  f32              @ 228096  (2048)
//   rm  [64]     f32              @ 230144  (256)
#define SM_WH   0
#define SM_WL   49536
#define SM_HB   99072
#define HB_STRIDE 136
#define HB_BUF  (2 * 64 * 136)          // elems per buffer (hi then lo)
#define SM_RED  203520
#define SM_GI   221952
#define SM_HP   228096
#define SM_RM   230144
#define SM_TOT  230400

__global__ void __launch_bounds__(256, 1)
phase2(const float* __restrict__ bhn, float* __restrict__ out) {
    extern __shared__ __align__(16) char smraw[];
    __nv_bfloat16* Wh  = (__nv_bfloat16*)(smraw + SM_WH);
    __nv_bfloat16* Wl  = (__nv_bfloat16*)(smraw + SM_WL);
    __nv_bfloat16* HB  = (__nv_bfloat16*)(smraw + SM_HB);
    float* red   = (float*)(smraw + SM_RED);
    float* gi_sm = (float*)(smraw + SM_GI);
    float* hp_sm = (float*)(smraw + SM_HP);
    float* rm_sm = (float*)(smraw + SM_RM);

    const int tid = threadIdx.x, warp = tid >> 5, lane = tid & 31;
    const int g = lane >> 2, t = lane & 3;
    const int j0 = blockIdx.x * 8;
    const int mg = warp >> 2, ks = warp & 3;        // m-group (32 rows), K-split quarter

    // stage W_h slice (24 gh-columns, split-bf16) once; resident all 512 steps
    for (int i = tid; i < 3072; i += 256) {         // 24 rows x 128 uint4
        int nl = i >> 7, o8 = (i & 127) << 3;
        size_t ng = (size_t)((nl >> 3) * 1024 + j0 + (nl & 7)) * 1024 + o8;
        *(uint4*)&Wh[nl * 1032 + o8] = *(const uint4*)&g_whh[ng];
        *(uint4*)&Wl[nl * 1032 + o8] = *(const uint4*)&g_whl[ng];
    }
    const float bhn0 = bhn[j0 + 2 * t], bhn1 = bhn[j0 + 2 * t + 1];
    __syncthreads();

    const int cp_row = tid >> 2, cp_q = tid & 3;    // for h chunk staging

    for (int s = 0; s < 512; ++s) {
        const int par = s & 1;
        const __nv_bfloat16* Ahg = g_hhi[par];
        const __nv_bfloat16* Alg = g_hlo[par];

        // ---- issue chunks 0..2 (+ epilogue prefetch bundled with chunk 0) ----
#pragma unroll
        for (int c = 0; c < 3; ++c) {
            __nv_bfloat16* dhi = HB + (c % 3) * HB_BUF;
            __nv_bfloat16* dlo = dhi + 64 * HB_STRIDE;
            const __nv_bfloat16* shi = Ahg + cp_row * 1024 + c * 128;
            const __nv_bfloat16* slo = Alg + cp_row * 1024 + c * 128;
#pragma unroll
            for (int s4 = 0; s4 < 4; ++s4) {
                int seg = cp_q * 4 + s4;
                cpa16(dhi + cp_row * HB_STRIDE + seg * 8, shi + seg * 8);
                cpa16(dlo + cp_row * HB_STRIDE + seg * 8, slo + seg * 8);
            }
            if (c == 0) {
                if (tid < 192) {        // gi slice: 64 rows x 3 gates x 2 halves
#pragma unroll
                    for (int u = 0; u < 2; ++u) {
                        int o = tid * 2 + u;
                        int row = o / 6, rem = o % 6, gate = rem >> 1, half = rem & 1;
                        cpa16(gi_sm + row * 24 + gate * 8 + half * 4,
                              g_gi + ((size_t)s * 64 + row) * 3072 + gate * 1024 + j0 + half * 4);
                    }
                } else {                // h_prev fp32 slice: 64 rows x 2 halves
                    int k = tid - 192;
#pragma unroll
                    for (int u = 0; u < 2; ++u)
                        cpa16(hp_sm + k * 8 + u * 4,
                              g_hf[par] + k * 1024 + j0 + u * 4);
                }
                if (tid < 16) {         // reset mask for step s+1
                    int sn = (s + 1 < 512) ? s + 1 : 511;
                    cpa16(rm_sm + tid * 4, g_rmask + sn * 64 + tid * 4);
                }
            }
            cpcommit();
        }

        float acc[2][3][4];
#pragma unroll
        for (int mi = 0; mi < 2; ++mi)
#pragma unroll
            for (int q = 0; q < 3; ++q)
#pragma unroll
                for (int e = 0; e < 4; ++e) acc[mi][q][e] = 0.f;

        // ---- 8 chunks of 128 K-cols, 3-buffer pipeline ----
        for (int c = 0; c < 8; ++c) {
            if (c <= 5) cpwait<2>(); else if (c == 6) cpwait<1>(); else cpwait<0>();
            __syncthreads();
            if (c + 2 < 8) {            // refill buffer (c+2)%3 (= buf of c-1, consumed)
                int cn = c + 2;
                __nv_bfloat16* dhi = HB + (cn % 3) * HB_BUF;
                __nv_bfloat16* dlo = dhi + 64 * HB_STRIDE;
                const __nv_bfloat16* shi = Ahg + cp_row * 1024 + cn * 128;
                const __nv_bfloat16* slo = Alg + cp_row * 1024 + cn * 128;
#pragma unroll
                for (int s4 = 0; s4 < 4; ++s4) {
                    int seg = cp_q * 4 + s4;
                    cpa16(dhi + cp_row * HB_STRIDE + seg * 8, shi + seg * 8);
                    cpa16(dlo + cp_row * HB_STRIDE + seg * 8, slo + seg * 8);
                }
                cpcommit();
            }
            const __nv_bfloat16* hb_hi = HB + (c % 3) * HB_BUF;
            const __nv_bfloat16* hb_lo = hb_hi + 64 * HB_STRIDE;
#pragma unroll
            for (int k16 = 0; k16 < 2; ++k16) {
                int col = ks * 32 + k16 * 16 + 2 * t;
                U32 ah[2][4], al[2][4];
#pragma unroll
                for (int mi = 0; mi < 2; ++mi) {
                    int r = mg * 32 + mi * 16 + g;
                    ah[mi][0] = *(const U32*)&hb_hi[r * HB_STRIDE + col];
                    ah[mi][1] = *(const U32*)&hb_hi[(r + 8) * HB_STRIDE + col];
                    ah[mi][2] = *(const U32*)&hb_hi[r * HB_STRIDE + col + 8];
                    ah[mi][3] = *(const U32*)&hb_hi[(r + 8) * HB_STRIDE + col + 8];
                    al[mi][0] = *(const U32*)&hb_lo[r * HB_STRIDE + col];
                    al[mi][1] = *(const U32*)&hb_lo[(r + 8) * HB_STRIDE + col];
                    al[mi][2] = *(const U32*)&hb_lo[r * HB_STRIDE + col + 8];
                    al[mi][3] = *(const U32*)&hb_lo[(r + 8) * HB_STRIDE + col + 8];
                }
                int gk = c * 128 + col;
#pragma unroll
                for (int gate = 0; gate < 3; ++gate) {
                    int nl = gate * 8 + g;
                    U32 bh[2] = {*(const U32*)&Wh[nl * 1032 + gk], *(const U32*)&Wh[nl * 1032 + gk + 8]};
                    U32 bl[2] = {*(const U32*)&Wl[nl * 1032 + gk], *(const U32*)&Wl[nl * 1032 + gk + 8]};
#pragma unroll
                    for (int mi = 0; mi < 2; ++mi) {
                        mma16816(acc[mi][gate], ah[mi], bh);
                        mma16816(acc[mi][gate], ah[mi], bl);
                        mma16816(acc[mi][gate], al[mi], bh);
                    }
                }
            }
        }

        // ---- reduce K-split partials ----
        if (ks != 0) {
#pragma unroll
            for (int mi = 0; mi < 2; ++mi)
#pragma unroll
                for (int gate = 0; gate < 3; ++gate)
#pragma unroll
                    for (int e = 0; e < 4; ++e) {
                        int row = mg * 32 + mi * 16 + g + ((e & 2) ? 8 : 0);
                        red[((ks - 1) * 64 + row) * 24 + gate * 8 + 2 * t + (e & 1)] = acc[mi][gate][e];
                    }
        }
        __syncthreads();

        // ---- epilogue (ks==0 warps: 64 rows x 8 cols) ----
        if (ks == 0) {
#pragma unroll
            for (int mi = 0; mi < 2; ++mi)
#pragma unroll
                for (int e = 0; e < 4; ++e) {
                    int row = mg * 32 + mi * 16 + g + ((e & 2) ? 8 : 0);
                    int jc = 2 * t + (e & 1);
                    int j = j0 + jc;
                    float ar = acc[mi][0][e], az = acc[mi][1][e], an = acc[mi][2][e];
#pragma unroll
                    for (int p = 0; p < 3; ++p) {
                        ar += red[(p * 64 + row) * 24 + jc];
                        az += red[(p * 64 + row) * 24 + 8 + jc];
                        an += red[(p * 64 + row) * 24 + 16 + jc];
                    }
                    float ir = gi_sm[row * 24 + jc];
                    float iz = gi_sm[row * 24 + 8 + jc];
                    float inn = gi_sm[row * 24 + 16 + jc];
                    float hp = hp_sm[row * 8 + jc];
                    float r = 1.f / (1.f + __expf(-(ir + ar)));
                    float z = 1.f / (1.f + __expf(-(iz + az)));
                    float bn = (e & 1) ? bhn1 : bhn0;
                    float n = tanh_fast(inn + r * (an + bn));
                    float hn = n + z * (hp - n);
                    out[((size_t)s * 64 + row) * 1024 + j] = hn;
                    if (s + 1 < 512) {
                        float hm = hn * rm_sm[row];
                        g_hf[1 - par][row * 1024 + j] = hm;
                        __nv_bfloat16 h = bhi(hm);
                        g_hhi[1 - par][row * 1024 + j] = h;
                        g_hlo[1 - par][row * 1024 + j] = blo(hm, h);
                    }
                }
        }
        __syncthreads();
        if (tid == 0) {
            __threadfence();
            atomicAdd(&g_bar, 1);
            int tgt = P2_CTAS * (s + 1);
            while (*(volatile int*)&g_bar < tgt) __nanosleep(32);
            __threadfence();
        }
        __syncthreads();
    }
}

extern "C" void kernel_launch(void* const* d_in, const int* in_sizes, int n_in,
                              void* d_out, int out_size) {
    const float*         ins  = (const float*)d_in[0];
    const unsigned char* rs   = (const unsigned char*)d_in[1];
    const float*         Wi   = (const float*)d_in[2];
    const float*         bi   = (const float*)d_in[3];
    const float*         Whm  = (const float*)d_in[4];
    const float*         bhn  = (const float*)d_in[5];
    float*               out  = (float*)d_out;
    (void)in_sizes; (void)n_in; (void)out_size;

    cudaFuncSetAttribute(phase2, cudaFuncAttributeMaxDynamicSharedMemorySize, SM_TOT);

    initk<<<64, 256>>>(rs);
    rmaskk<<<128, 256>>>(rs);
    convw<<<(3072 * 1024 + 255) / 256, 256>>>(Whm);
    phase1<<<dim3(24, 256), 256>>>(ins, Wi, bi);
    phase2<<<P2_CTAS, 256, SM_TOT>>>(bhn, out);
}

// round 14
// speedup vs baseline: 1.2365x; 1.1564x over previous
#include <cuda_runtime.h>
#include <cuda_bf16.h>
#include <cstdint>
#include <math.h>

#define DI __device__ __forceinline__
typedef unsigned U32;

// T=512, B=64, H=1024, 3H=3072, M=T*B=32768
__device__ float          g_gi[100663296];        // [32768][3072]
__device__ __nv_bfloat16  g_whh[3145728];         // W_h^T hi [3072][1024]
__device__ __nv_bfloat16  g_whl[3145728];         // W_h^T lo
__device__ __nv_bfloat16  g_wih[3145728];         // W_i^T hi [3072][1024]
__device__ __nv_bfloat16  g_wil[3145728];         // W_i^T lo
__device__ __nv_bfloat16  g_aih[33554432];        // ins hi [32768][1024]
__device__ __nv_bfloat16  g_ail[33554432];        // ins lo
__device__ __nv_bfloat16  g_hhi[2][65536];        // masked h split-bf16 [par][64][1024]
__device__ __nv_bfloat16  g_hlo[2][65536];
__device__ float          g_rmask[32768];         // [512][64]: reset?0:1
__device__ int            g_wrcnt[513][8];        // producer flags per col-group
__device__ int            g_rdcnt[513];           // consume-done per step
__device__ int            g_rmode;                // 0=int32 1=uint8 2=float32

DI void mma16816(float d[4], const U32 a[4], const U32 b[2]) {
    asm volatile(
        "mma.sync.aligned.m16n8k16.row.col.f32.bf16.bf16.f32 "
        "{%0,%1,%2,%3},{%4,%5,%6,%7},{%8,%9},{%0,%1,%2,%3};\n"
        : "+f"(d[0]), "+f"(d[1]), "+f"(d[2]), "+f"(d[3])
        : "r"(a[0]), "r"(a[1]), "r"(a[2]), "r"(a[3]), "r"(b[0]), "r"(b[1]));
}
DI __nv_bfloat16 bhi(float x) { return __float2bfloat16(x); }
DI __nv_bfloat16 blo(float x, __nv_bfloat16 h) { return __float2bfloat16(x - __bfloat162float(h)); }

DI void cpa16(void* dst, const void* src) {
    unsigned d = (unsigned)__cvta_generic_to_shared(dst);
    asm volatile("cp.async.cg.shared.global [%0], [%1], 16;\n" :: "r"(d), "l"(src));
}
DI void cpcommit() { asm volatile("cp.async.commit_group;\n" ::: "memory"); }
template<int N> DI void cpwait() { asm volatile("cp.async.wait_group %0;\n" :: "n"(N) : "memory"); }
DI float tanh_fast(float x) { float y; asm("tanh.approx.f32 %0, %1;\n" : "=f"(y) : "f"(x)); return y; }
DI int ldvol(const int* p) { return *(volatile const int*)p; }

// -------- init: zero h buffers + flags, probe resets dtype --------
__global__ void initk(const unsigned char* __restrict__ rs) {
    int i = blockIdx.x * blockDim.x + threadIdx.x;
    int nt = gridDim.x * blockDim.x;
    if (i == 0) {
        int mode = 0;
        for (int b = 0; b < 16384; ++b) {
            if ((b & 3) == 3 && rs[b] == 0x3F) { mode = 2; break; }
            if ((b & 3) != 0 && rs[b] != 0 && mode == 0) mode = 1;
        }
        g_rmode = mode;
    }
    for (int k = i; k < 2 * 65536; k += nt) {
        (&g_hhi[0][0])[k] = __float2bfloat16(0.0f);
        (&g_hlo[0][0])[k] = __float2bfloat16(0.0f);
    }
    for (int k = i; k < 513 * 8; k += nt) (&g_wrcnt[0][0])[k] = (k < 8) ? 16 : 0;
    for (int k = i; k < 513; k += nt) g_rdcnt[k] = 0;
}

// -------- resets -> float mask --------
__global__ void rmaskk(const unsigned char* __restrict__ rs) {
    int i = blockIdx.x * blockDim.x + threadIdx.x;
    if (i >= 32768) return;
    int mode = g_rmode;
    int v = (mode == 1) ? rs[i] : (mode == 0) ? rs[i * 4] : rs[i * 4 + 3];
    g_rmask[i] = v ? 0.f : 1.f;
}

// -------- split conversions --------
__global__ void convA(const float* __restrict__ A) {
    int i = blockIdx.x * 256 + threadIdx.x;
    if (i >= 33554432) return;
    float x = A[i];
    __nv_bfloat16 h = bhi(x);
    g_aih[i] = h; g_ail[i] = blo(x, h);
}
__global__ void convW(const float* __restrict__ W, __nv_bfloat16* __restrict__ oh,
                      __nv_bfloat16* __restrict__ ol) {
    int idx = blockIdx.x * 256 + threadIdx.x;
    if (idx >= 3072 * 1024) return;
    int k = idx / 3072, n = idx % 3072;
    float x = W[idx];
    __nv_bfloat16 h = bhi(x);
    oh[(size_t)n * 1024 + k] = h;
    ol[(size_t)n * 1024 + k] = blo(x, h);
}

// -------- phase 1: gi = ins @ W_i + b_i, pre-split bf16, double-buffered ----
// smem per buffer: Ah@0 Al@10240 Bh@20480 Bl@30720 ([128][40] bf16 each)
#define P1_BUF 40960
__global__ void __launch_bounds__(256, 1)
phase1(const float* __restrict__ bias) {
    extern __shared__ __align__(16) char sm[];
    const int tid = threadIdx.x, warp = tid >> 5, lane = tid & 31;
    const int g = lane >> 2, t = lane & 3;
    const int m0 = blockIdx.y * 128, n0 = blockIdx.x * 128;
    const int wm = (warp & 3) * 32, wn = (warp >> 2) * 64;
    const int row = tid >> 1, half = tid & 1;

    float acc[2][8][4];
#pragma unroll
    for (int mi = 0; mi < 2; ++mi)
#pragma unroll
        for (int ni = 0; ni < 8; ++ni)
#pragma unroll
            for (int e = 0; e < 4; ++e) acc[mi][ni][e] = 0.f;

    auto issue = [&](int buf, int ki) {
        char* b = sm + buf * P1_BUF;
        size_t am = (size_t)(m0 + row) * 1024 + ki;
        size_t bn = (size_t)(n0 + row) * 1024 + ki;
#pragma unroll
        for (int ss = 0; ss < 2; ++ss) {
            int seg = half * 2 + ss;
            cpa16(b + row * 80 + seg * 16,         g_aih + am + seg * 8);
            cpa16(b + 10240 + row * 80 + seg * 16, g_ail + am + seg * 8);
            cpa16(b + 20480 + row * 80 + seg * 16, g_wih + bn + seg * 8);
            cpa16(b + 30720 + row * 80 + seg * 16, g_wil + bn + seg * 8);
        }
    };

    issue(0, 0); cpcommit();
    for (int i = 0; i < 32; ++i) {
        if (i + 1 < 32) { issue((i + 1) & 1, (i + 1) * 32); cpcommit(); }
        if (i + 1 < 32) cpwait<1>(); else cpwait<0>();
        __syncthreads();
        const __nv_bfloat16* Ah = (const __nv_bfloat16*)(sm + (i & 1) * P1_BUF);
        const __nv_bfloat16* Al = Ah + 5120;
        const __nv_bfloat16* Bh = Ah + 10240;
        const __nv_bfloat16* Bl = Ah + 15360;
#pragma unroll
        for (int k16 = 0; k16 < 2; ++k16) {
            int kk = k16 * 16 + 2 * t;
            U32 ah[2][4], al[2][4];
#pragma unroll
            for (int mi = 0; mi < 2; ++mi) {
                int r = wm + mi * 16 + g;
                ah[mi][0] = *(const U32*)&Ah[r * 40 + kk];       ah[mi][1] = *(const U32*)&Ah[(r + 8) * 40 + kk];
                ah[mi][2] = *(const U32*)&Ah[r * 40 + kk + 8];   ah[mi][3] = *(const U32*)&Ah[(r + 8) * 40 + kk + 8];
                al[mi][0] = *(const U32*)&Al[r * 40 + kk];       al[mi][1] = *(const U32*)&Al[(r + 8) * 40 + kk];
                al[mi][2] = *(const U32*)&Al[r * 40 + kk + 8];   al[mi][3] = *(const U32*)&Al[(r + 8) * 40 + kk + 8];
            }
#pragma unroll
            for (int ni = 0; ni < 8; ++ni) {
                int nn = wn + ni * 8 + g;
                U32 bh[2] = {*(const U32*)&Bh[nn * 40 + kk], *(const U32*)&Bh[nn * 40 + kk + 8]};
                U32 bl[2] = {*(const U32*)&Bl[nn * 40 + kk], *(const U32*)&Bl[nn * 40 + kk + 8]};
#pragma unroll
                for (int mi = 0; mi < 2; ++mi) {
                    mma16816(acc[mi][ni], ah[mi], bh);
                    mma16816(acc[mi][ni], ah[mi], bl);
                    mma16816(acc[mi][ni], al[mi], bh);
                }
            }
        }
        __syncthreads();
    }
#pragma unroll
    for (int mi = 0; mi < 2; ++mi)
#pragma unroll
        for (int ni = 0; ni < 8; ++ni)
#pragma unroll
            for (int e = 0; e < 4; ++e) {
                int r2 = m0 + wm + mi * 16 + g + ((e & 2) ? 8 : 0);
                int c2 = n0 + wn + ni * 8 + 2 * t + (e & 1);
                g_gi[(size_t)r2 * 3072 + c2] = acc[mi][ni][e] + bias[c2];
            }
}

// -------- phase 2: persistent recurrence, distributed dataflow flags --------
#define P2_CTAS 128
#define SM_WH   0
#define SM_WL   49536
#define SM_HB   99072
#define HB_STRIDE 136
#define HB_BUF  (2 * 64 * 136)
#define SM_RED  203520
#define SM_GI   221952
#define SM_HPH  228096
#define SM_HPL  229120
#define SM_RM   230144
#define SM_TOT  230400

__global__ void __launch_bounds__(256, 1)
phase2(const float* __restrict__ bhn, float* __restrict__ out) {
    extern __shared__ __align__(16) char smraw[];
    __nv_bfloat16* Wh  = (__nv_bfloat16*)(smraw + SM_WH);
    __nv_bfloat16* Wl  = (__nv_bfloat16*)(smraw + SM_WL);
    __nv_bfloat16* HB  = (__nv_bfloat16*)(smraw + SM_HB);
    float* red   = (float*)(smraw + SM_RED);
    float* gi_sm = (float*)(smraw + SM_GI);
    __nv_bfloat16* hph = (__nv_bfloat16*)(smraw + SM_HPH);
    __nv_bfloat16* hpl = (__nv_bfloat16*)(smraw + SM_HPL);
    float* rm_sm = (float*)(smraw + SM_RM);

    const int tid = threadIdx.x, warp = tid >> 5, lane = tid & 31;
    const int g = lane >> 2, t = lane & 3;
    const int j0 = blockIdx.x * 8, grp = blockIdx.x >> 4;
    const int mg = warp & 1, ks = warp >> 1;        // epi warps 0,1 -> SMSP 0,1

    for (int i = tid; i < 3072; i += 256) {         // W_h slice resident
        int nl = i >> 7, o8 = (i & 127) << 3;
        size_t ng = (size_t)((nl >> 3) * 1024 + j0 + (nl & 7)) * 1024 + o8;
        *(uint4*)&Wh[nl * 1032 + o8] = *(const uint4*)&g_whh[ng];
        *(uint4*)&Wl[nl * 1032 + o8] = *(const uint4*)&g_whl[ng];
    }
    const float bhn0 = bhn[j0 + 2 * t], bhn1 = bhn[j0 + 2 * t + 1];
    __syncthreads();

    const int cp_row = tid >> 2, cp_q = tid & 3;

    for (int s = 0; s < 512; ++s) {
        const int par = s & 1;
        const __nv_bfloat16* Ahg = g_hhi[par];
        const __nv_bfloat16* Alg = g_hlo[par];

        auto issue_chunk = [&](int buf, int cid) {
            __nv_bfloat16* dhi = HB + buf * HB_BUF;
            __nv_bfloat16* dlo = dhi + 64 * HB_STRIDE;
            const __nv_bfloat16* shi = Ahg + cp_row * 1024 + cid * 128;
            const __nv_bfloat16* slo = Alg + cp_row * 1024 + cid * 128;
#pragma unroll
            for (int s4 = 0; s4 < 4; ++s4) {
                int seg = cp_q * 4 + s4;
                cpa16(dhi + cp_row * HB_STRIDE + seg * 8, shi + seg * 8);
                cpa16(dlo + cp_row * HB_STRIDE + seg * 8, slo + seg * 8);
            }
        };

        // preload 2 chunks (rotated start = own group), bundle epilogue prefetch
#pragma unroll
        for (int p = 0; p < 2; ++p) {
            int cid = (grp + p) & 7;
            if (tid == 0) while (ldvol(&g_wrcnt[s][cid]) < 16) __nanosleep(16);
            __syncthreads();
            issue_chunk(p, cid);
            if (p == 0) {
                if (tid < 192) {        // gi slice: 64 rows x 3 gates x 2 halves
#pragma unroll
                    for (int u = 0; u < 2; ++u) {
                        int o = tid * 2 + u;
                        int rrow = o / 6, rem = o % 6, gate = rem >> 1, hf = rem & 1;
                        cpa16(gi_sm + rrow * 24 + gate * 8 + hf * 4,
                              g_gi + ((size_t)s * 64 + rrow) * 3072 + gate * 1024 + j0 + hf * 4);
                    }
                } else {                // h_prev hi+lo: 64 threads x (16B hi + 16B lo)
                    int k = tid - 192;
                    cpa16(hph + k * 8, g_hhi[par] + k * 1024 + j0);
                    cpa16(hpl + k * 8, g_hlo[par] + k * 1024 + j0);
                }
                if (tid < 16) {         // reset mask for step s+1
                    int sn = (s + 1 < 512) ? s + 1 : 511;
                    cpa16(rm_sm + tid * 4, g_rmask + sn * 64 + tid * 4);
                }
            }
            cpcommit();
        }

        float acc[2][3][4];
#pragma unroll
        for (int mi = 0; mi < 2; ++mi)
#pragma unroll
            for (int q = 0; q < 3; ++q)
#pragma unroll
                for (int e = 0; e < 4; ++e) acc[mi][q][e] = 0.f;

        for (int c = 0; c < 8; ++c) {
            if (c + 2 < 8) {
                int cid = (grp + c + 2) & 7;
                if (tid == 0) while (ldvol(&g_wrcnt[s][cid]) < 16) __nanosleep(16);
                __syncthreads();
                issue_chunk((c + 2) % 3, cid);
                cpcommit();
            }
            if (c + 2 < 8) cpwait<2>(); else if (c + 1 < 8) cpwait<1>(); else cpwait<0>();
            __syncthreads();
            const int cid = (grp + c) & 7;
            const __nv_bfloat16* hb_hi = HB + (c % 3) * HB_BUF;
            const __nv_bfloat16* hb_lo = hb_hi + 64 * HB_STRIDE;
#pragma unroll
            for (int k16 = 0; k16 < 2; ++k16) {
                int col = ks * 32 + k16 * 16 + 2 * t;
                U32 ah[2][4], al[2][4];
#pragma unroll
                for (int mi = 0; mi < 2; ++mi) {
                    int r = mg * 32 + mi * 16 + g;
                    ah[mi][0] = *(const U32*)&hb_hi[r * HB_STRIDE + col];
                    ah[mi][1] = *(const U32*)&hb_hi[(r + 8) * HB_STRIDE + col];
                    ah[mi][2] = *(const U32*)&hb_hi[r * HB_STRIDE + col + 8];
                    ah[mi][3] = *(const U32*)&hb_hi[(r + 8) * HB_STRIDE + col + 8];
                    al[mi][0] = *(const U32*)&hb_lo[r * HB_STRIDE + col];
                    al[mi][1] = *(const U32*)&hb_lo[(r + 8) * HB_STRIDE + col];
                    al[mi][2] = *(const U32*)&hb_lo[r * HB_STRIDE + col + 8];
                    al[mi][3] = *(const U32*)&hb_lo[(r + 8) * HB_STRIDE + col + 8];
                }
                int gk = cid * 128 + col;
#pragma unroll
                for (int gate = 0; gate < 3; ++gate) {
                    int nl = gate * 8 + g;
                    U32 bh[2] = {*(const U32*)&Wh[nl * 1032 + gk], *(const U32*)&Wh[nl * 1032 + gk + 8]};
                    U32 bl[2] = {*(const U32*)&Wl[nl * 1032 + gk], *(const U32*)&Wl[nl * 1032 + gk + 8]};
#pragma unroll
                    for (int mi = 0; mi < 2; ++mi) {
                        mma16816(acc[mi][gate], ah[mi], bh);
                        mma16816(acc[mi][gate], ah[mi], bl);
                        mma16816(acc[mi][gate], al[mi], bh);
                    }
                }
            }
        }

        if (ks != 0) {
#pragma unroll
            for (int mi = 0; mi < 2; ++mi)
#pragma unroll
                for (int gate = 0; gate < 3; ++gate)
#pragma unroll
                    for (int e = 0; e < 4; ++e) {
                        int rrow = mg * 32 + mi * 16 + g + ((e & 2) ? 8 : 0);
                        red[((ks - 1) * 64 + rrow) * 24 + gate * 8 + 2 * t + (e & 1)] = acc[mi][gate][e];
                    }
        }
        __syncthreads();
        if (tid == 0) {
            atomicAdd(&g_rdcnt[s], 1);                       // done reading h[s]
            if (s >= 1) while (ldvol(&g_rdcnt[s - 1]) < P2_CTAS) __nanosleep(16);
        }
        __syncthreads();

        if (ks == 0) {
#pragma unroll
            for (int mi = 0; mi < 2; ++mi)
#pragma unroll
                for (int e = 0; e < 4; ++e) {
                    int rrow = mg * 32 + mi * 16 + g + ((e & 2) ? 8 : 0);
                    int jc = 2 * t + (e & 1);
                    int j = j0 + jc;
                    float ar = acc[mi][0][e], az = acc[mi][1][e], an = acc[mi][2][e];
#pragma unroll
                    for (int p = 0; p < 3; ++p) {
                        ar += red[(p * 64 + rrow) * 24 + jc];
                        az += red[(p * 64 + rrow) * 24 + 8 + jc];
                        an += red[(p * 64 + rrow) * 24 + 16 + jc];
                    }
                    float ir = gi_sm[rrow * 24 + jc];
                    float iz = gi_sm[rrow * 24 + 8 + jc];
                    float inn = gi_sm[rrow * 24 + 16 + jc];
                    float hp = __bfloat162float(hph[rrow * 8 + jc]) + __bfloat162float(hpl[rrow * 8 + jc]);
                    float r = 1.f / (1.f + __expf(-(ir + ar)));
                    float z = 1.f / (1.f + __expf(-(iz + az)));
                    float bn = (e & 1) ? bhn1 : bhn0;
                    float n = tanh_fast(inn + r * (an + bn));
                    float hn = n + z * (hp - n);
                    out[((size_t)s * 64 + rrow) * 1024 + j] = hn;
                    if (s + 1 < 512) {
                        float hm = hn * rm_sm[rrow];
                        __nv_bfloat16 h = bhi(hm);
                        g_hhi[1 - par][rrow * 1024 + j] = h;
                        g_hlo[1 - par][rrow * 1024 + j] = blo(hm, h);
                    }
                }
        }
        __threadfence();
        __syncthreads();
        if (tid == 0) atomicAdd(&g_wrcnt[s + 1][grp], 1);    // h[s+1] cols ready
    }
}

extern "C" void kernel_launch(void* const* d_in, const int* in_sizes, int n_in,
                              void* d_out, int out_size) {
    const float*         ins  = (const float*)d_in[0];
    const unsigned char* rs   = (const unsigned char*)d_in[1];
    const float*         Wi   = (const float*)d_in[2];
    const float*         bi   = (const float*)d_in[3];
    const float*         Whm  = (const float*)d_in[4];
    const float*         bhn  = (const float*)d_in[5];
    float*               out  = (float*)d_out;
    (void)in_sizes; (void)n_in; (void)out_size;

    __nv_bfloat16 *whh, *whl, *wih, *wil;
    cudaGetSymbolAddress((void**)&whh, g_whh);
    cudaGetSymbolAddress((void**)&whl, g_whl);
    cudaGetSymbolAddress((void**)&wih, g_wih);
    cudaGetSymbolAddress((void**)&wil, g_wil);

    cudaFuncSetAttribute(phase1, cudaFuncAttributeMaxDynamicSharedMemorySize, 2 * P1_BUF);
    cudaFuncSetAttribute(phase2, cudaFuncAttributeMaxDynamicSharedMemorySize, SM_TOT);

    initk<<<64, 256>>>(rs);
    rmaskk<<<128, 256>>>(rs);
    convA<<<(33554432 + 255) / 256, 256>>>(ins);
    convW<<<(3145728 + 255) / 256, 256>>>(Wi, wih, wil);
    convW<<<(3145728 + 255) / 256, 256>>>(Whm, whh, whl);
    phase1<<<dim3(24, 256), 256, 2 * P1_BUF>>>(bi);
    phase2<<<P2_CTAS, 256, SM_TOT>>>(bhn, out);
}

// round 15
// speedup vs baseline: 1.4071x; 1.1380x over previous
#include <cuda_runtime.h>
#include <cuda_bf16.h>
#include <cstdint>
#include <math.h>

#define DI __device__ __forceinline__
typedef unsigned U32;

// T=512, B=64, H=1024, 3H=3072, M=T*B=32768
__device__ float          g_gi[100663296];        // [32768][3072]
__device__ __nv_bfloat16  g_whh[3145728];         // W_h^T hi [3072][1024]
__device__ __nv_bfloat16  g_whl[3145728];         // W_h^T lo
__device__ __nv_bfloat16  g_wih[3145728];         // W_i^T hi [3072][1024]
__device__ __nv_bfloat16  g_wil[3145728];         // W_i^T lo
__device__ __nv_bfloat16  g_aih[33554432];        // ins hi [32768][1024]
__device__ __nv_bfloat16  g_ail[33554432];        // ins lo
__device__ __nv_bfloat16  g_hhi[3][65536];        // masked h split-bf16 [par3][64][1024]
__device__ __nv_bfloat16  g_hlo[3][65536];
__device__ float          g_rmask[32768];         // [512][64]: reset?0:1
__device__ int            g_wrcnt[513][8];        // producer flags per col-group
__device__ int            g_rdcnt[513];           // consume-done per step
__device__ int            g_rmode;                // 0=int32 1=uint8 2=float32

DI void mma16816(float d[4], const U32 a[4], const U32 b[2]) {
    asm volatile(
        "mma.sync.aligned.m16n8k16.row.col.f32.bf16.bf16.f32 "
        "{%0,%1,%2,%3},{%4,%5,%6,%7},{%8,%9},{%0,%1,%2,%3};\n"
        : "+f"(d[0]), "+f"(d[1]), "+f"(d[2]), "+f"(d[3])
        : "r"(a[0]), "r"(a[1]), "r"(a[2]), "r"(a[3]), "r"(b[0]), "r"(b[1]));
}
DI __nv_bfloat16 bhi(float x) { return __float2bfloat16(x); }
DI __nv_bfloat16 blo(float x, __nv_bfloat16 h) { return __float2bfloat16(x - __bfloat162float(h)); }

DI void cpa16(void* dst, const void* src) {
    unsigned d = (unsigned)__cvta_generic_to_shared(dst);
    asm volatile("cp.async.cg.shared.global [%0], [%1], 16;\n" :: "r"(d), "l"(src));
}
DI void cpcommit() { asm volatile("cp.async.commit_group;\n" ::: "memory"); }
template<int N> DI void cpwait() { asm volatile("cp.async.wait_group %0;\n" :: "n"(N) : "memory"); }
DI float tanh_fast(float x) { float y; asm("tanh.approx.f32 %0, %1;\n" : "=f"(y) : "f"(x)); return y; }
DI int ldvol(const int* p) { return *(volatile const int*)p; }

// -------- init: zero h buffers + flags, probe resets dtype --------
__global__ void initk(const unsigned char* __restrict__ rs) {
    int i = blockIdx.x * blockDim.x + threadIdx.x;
    int nt = gridDim.x * blockDim.x;
    if (i == 0) {
        int mode = 0;
        for (int b = 0; b < 16384; ++b) {
            if ((b & 3) == 3 && rs[b] == 0x3F) { mode = 2; break; }
            if ((b & 3) != 0 && rs[b] != 0 && mode == 0) mode = 1;
        }
        g_rmode = mode;
    }
    for (int k = i; k < 3 * 65536; k += nt) {
        (&g_hhi[0][0])[k] = __float2bfloat16(0.0f);
        (&g_hlo[0][0])[k] = __float2bfloat16(0.0f);
    }
    for (int k = i; k < 513 * 8; k += nt) (&g_wrcnt[0][0])[k] = (k < 8) ? 16 : 0;
    for (int k = i; k < 513; k += nt) g_rdcnt[k] = 0;
}

// -------- resets -> float mask --------
__global__ void rmaskk(const unsigned char* __restrict__ rs) {
    int i = blockIdx.x * blockDim.x + threadIdx.x;
    if (i >= 32768) return;
    int mode = g_rmode;
    int v = (mode == 1) ? rs[i] : (mode == 0) ? rs[i * 4] : rs[i * 4 + 3];
    g_rmask[i] = v ? 0.f : 1.f;
}

// -------- split conversions --------
__global__ void convA(const float* __restrict__ A) {
    int i = blockIdx.x * 256 + threadIdx.x;
    if (i >= 33554432) return;
    float x = A[i];
    __nv_bfloat16 h = bhi(x);
    g_aih[i] = h; g_ail[i] = blo(x, h);
}
__global__ void convW(const float* __restrict__ W, __nv_bfloat16* __restrict__ oh,
                      __nv_bfloat16* __restrict__ ol) {
    int idx = blockIdx.x * 256 + threadIdx.x;
    if (idx >= 3072 * 1024) return;
    int k = idx / 3072, n = idx % 3072;
    float x = W[idx];
    __nv_bfloat16 h = bhi(x);
    oh[(size_t)n * 1024 + k] = h;
    ol[(size_t)n * 1024 + k] = blo(x, h);
}

// -------- phase 1: gi = ins @ W_i + b_i, pre-split bf16, double-buffered ----
#define P1_BUF 40960
__global__ void __launch_bounds__(256, 1)
phase1(const float* __restrict__ bias) {
    extern __shared__ __align__(16) char sm[];
    const int tid = threadIdx.x, warp = tid >> 5, lane = tid & 31;
    const int g = lane >> 2, t = lane & 3;
    const int m0 = blockIdx.y * 128, n0 = blockIdx.x * 128;
    const int wm = (warp & 3) * 32, wn = (warp >> 2) * 64;
    const int row = tid >> 1, half = tid & 1;

    float acc[2][8][4];
#pragma unroll
    for (int mi = 0; mi < 2; ++mi)
#pragma unroll
        for (int ni = 0; ni < 8; ++ni)
#pragma unroll
            for (int e = 0; e < 4; ++e) acc[mi][ni][e] = 0.f;

    auto issue = [&](int buf, int ki) {
        char* b = sm + buf * P1_BUF;
        size_t am = (size_t)(m0 + row) * 1024 + ki;
        size_t bn = (size_t)(n0 + row) * 1024 + ki;
#pragma unroll
        for (int ss = 0; ss < 2; ++ss) {
            int seg = half * 2 + ss;
            cpa16(b + row * 80 + seg * 16,         g_aih + am + seg * 8);
            cpa16(b + 10240 + row * 80 + seg * 16, g_ail + am + seg * 8);
            cpa16(b + 20480 + row * 80 + seg * 16, g_wih + bn + seg * 8);
            cpa16(b + 30720 + row * 80 + seg * 16, g_wil + bn + seg * 8);
        }
    };

    issue(0, 0); cpcommit();
    for (int i = 0; i < 32; ++i) {
        if (i + 1 < 32) { issue((i + 1) & 1, (i + 1) * 32); cpcommit(); }
        if (i + 1 < 32) cpwait<1>(); else cpwait<0>();
        __syncthreads();
        const __nv_bfloat16* Ah = (const __nv_bfloat16*)(sm + (i & 1) * P1_BUF);
        const __nv_bfloat16* Al = Ah + 5120;
        const __nv_bfloat16* Bh = Ah + 10240;
        const __nv_bfloat16* Bl = Ah + 15360;
#pragma unroll
        for (int k16 = 0; k16 < 2; ++k16) {
            int kk = k16 * 16 + 2 * t;
            U32 ah[2][4], al[2][4];
#pragma unroll
            for (int mi = 0; mi < 2; ++mi) {
                int r = wm + mi * 16 + g;
                ah[mi][0] = *(const U32*)&Ah[r * 40 + kk];       ah[mi][1] = *(const U32*)&Ah[(r + 8) * 40 + kk];
                ah[mi][2] = *(const U32*)&Ah[r * 40 + kk + 8];   ah[mi][3] = *(const U32*)&Ah[(r + 8) * 40 + kk + 8];
                al[mi][0] = *(const U32*)&Al[r * 40 + kk];       al[mi][1] = *(const U32*)&Al[(r + 8) * 40 + kk];
                al[mi][2] = *(const U32*)&Al[r * 40 + kk + 8];   al[mi][3] = *(const U32*)&Al[(r + 8) * 40 + kk + 8];
            }
#pragma unroll
            for (int ni = 0; ni < 8; ++ni) {
                int nn = wn + ni * 8 + g;
                U32 bh[2] = {*(const U32*)&Bh[nn * 40 + kk], *(const U32*)&Bh[nn * 40 + kk + 8]};
                U32 bl[2] = {*(const U32*)&Bl[nn * 40 + kk], *(const U32*)&Bl[nn * 40 + kk + 8]};
#pragma unroll
                for (int mi = 0; mi < 2; ++mi) {
                    mma16816(acc[mi][ni], ah[mi], bh);
                    mma16816(acc[mi][ni], ah[mi], bl);
                    mma16816(acc[mi][ni], al[mi], bh);
                }
            }
        }
        __syncthreads();
    }
#pragma unroll
    for (int mi = 0; mi < 2; ++mi)
#pragma unroll
        for (int ni = 0; ni < 8; ++ni)
#pragma unroll
            for (int e = 0; e < 4; ++e) {
                int r2 = m0 + wm + mi * 16 + g + ((e & 2) ? 8 : 0);
                int c2 = n0 + wn + ni * 8 + 2 * t + (e & 1);
                g_gi[(size_t)r2 * 3072 + c2] = acc[mi][ni][e] + bias[c2];
            }
}

// -------- phase 2: persistent recurrence, 512 threads, dataflow flags --------
#define P2_CTAS 128
#define SM_WH   0
#define SM_WL   49536
#define SM_HB   99072
#define HB_STRIDE 136
#define HB_BUF  (2 * 64 * 136)
#define SM_RED  203520
#define SM_GI   221952
#define SM_HPH  228096
#define SM_HPL  229120
#define SM_RM   230144
#define SM_TOT  230400

__global__ void __launch_bounds__(512, 1)
phase2(const float* __restrict__ bhn, float* __restrict__ out) {
    extern __shared__ __align__(16) char smraw[];
    __nv_bfloat16* Wh  = (__nv_bfloat16*)(smraw + SM_WH);
    __nv_bfloat16* Wl  = (__nv_bfloat16*)(smraw + SM_WL);
    __nv_bfloat16* HB  = (__nv_bfloat16*)(smraw + SM_HB);
    float* red   = (float*)(smraw + SM_RED);
    float* gi_sm = (float*)(smraw + SM_GI);
    __nv_bfloat16* hph = (__nv_bfloat16*)(smraw + SM_HPH);
    __nv_bfloat16* hpl = (__nv_bfloat16*)(smraw + SM_HPL);
    float* rm_sm = (float*)(smraw + SM_RM);

    const int tid = threadIdx.x, warp = tid >> 5, lane = tid & 31;
    const int g = lane >> 2, t = lane & 3;
    const int j0 = blockIdx.x * 8, grp = blockIdx.x >> 4;
    const int mg = warp & 3, ks = warp >> 2;        // epi warps 0..3 -> SMSP 0..3

    for (int i = tid; i < 3072; i += 512) {         // W_h slice resident
        int nl = i >> 7, o8 = (i & 127) << 3;
        size_t ng = (size_t)((nl >> 3) * 1024 + j0 + (nl & 7)) * 1024 + o8;
        *(uint4*)&Wh[nl * 1032 + o8] = *(const uint4*)&g_whh[ng];
        *(uint4*)&Wl[nl * 1032 + o8] = *(const uint4*)&g_whl[ng];
    }
    const float bhn0 = bhn[j0 + 2 * t], bhn1 = bhn[j0 + 2 * t + 1];
    __syncthreads();

    const int cp_row = tid >> 3, cp_q = tid & 7;    // 512 threads: 64 rows x 8 segs

    for (int s = 0; s < 512; ++s) {
        const int par = s % 3, nxt = (s + 1) % 3;
        const __nv_bfloat16* Ahg = g_hhi[par];
        const __nv_bfloat16* Alg = g_hlo[par];

        auto issue_chunk = [&](int buf, int cid) {
            __nv_bfloat16* dhi = HB + buf * HB_BUF;
            __nv_bfloat16* dlo = dhi + 64 * HB_STRIDE;
            const __nv_bfloat16* shi = Ahg + cp_row * 1024 + cid * 128;
            const __nv_bfloat16* slo = Alg + cp_row * 1024 + cid * 128;
#pragma unroll
            for (int s4 = 0; s4 < 2; ++s4) {
                int seg = cp_q * 2 + s4;
                cpa16(dhi + cp_row * HB_STRIDE + seg * 8, shi + seg * 8);
                cpa16(dlo + cp_row * HB_STRIDE + seg * 8, slo + seg * 8);
            }
        };

        // preload 2 chunks (rotated start = own group), bundle epilogue prefetch
#pragma unroll
        for (int p = 0; p < 2; ++p) {
            int cid = (grp + p) & 7;
            if (tid == 0) while (ldvol(&g_wrcnt[s][cid]) < 16) __nanosleep(16);
            __syncthreads();
            issue_chunk(p, cid);
            if (p == 0) {
                if (tid < 384) {        // gi slice: 64 rows x 3 gates x 2 halves
                    int rrow = tid / 6, rem = tid % 6, gate = rem >> 1, hf = rem & 1;
                    cpa16(gi_sm + rrow * 24 + gate * 8 + hf * 4,
                          g_gi + ((size_t)s * 64 + rrow) * 3072 + gate * 1024 + j0 + hf * 4);
                } else if (tid < 448) { // h_prev hi: 64 rows x 16B
                    int k = tid - 384;
                    cpa16(hph + k * 8, g_hhi[par] + k * 1024 + j0);
                } else {                // h_prev lo
                    int k = tid - 448;
                    cpa16(hpl + k * 8, g_hlo[par] + k * 1024 + j0);
                }
                if (tid < 16) {         // reset mask for step s+1
                    int sn = (s + 1 < 512) ? s + 1 : 511;
                    cpa16(rm_sm + tid * 4, g_rmask + sn * 64 + tid * 4);
                }
            }
            cpcommit();
        }

        float acc[3][4];
#pragma unroll
        for (int q = 0; q < 3; ++q)
#pragma unroll
            for (int e = 0; e < 4; ++e) acc[q][e] = 0.f;

        for (int c = 0; c < 8; ++c) {
            if (c + 2 < 8) {
                int cid = (grp + c + 2) & 7;
                if (tid == 0) while (ldvol(&g_wrcnt[s][cid]) < 16) __nanosleep(16);
                __syncthreads();
                issue_chunk((c + 2) % 3, cid);
                cpcommit();
            }
            if (c + 2 < 8) cpwait<2>(); else if (c + 1 < 8) cpwait<1>(); else cpwait<0>();
            __syncthreads();
            const int cid = (grp + c) & 7;
            const __nv_bfloat16* hb_hi = HB + (c % 3) * HB_BUF;
            const __nv_bfloat16* hb_lo = hb_hi + 64 * HB_STRIDE;
#pragma unroll
            for (int k16 = 0; k16 < 2; ++k16) {
                int col = ks * 32 + k16 * 16 + 2 * t;
                int r = mg * 16 + g;
                U32 ah[4], al[4];
                ah[0] = *(const U32*)&hb_hi[r * HB_STRIDE + col];
                ah[1] = *(const U32*)&hb_hi[(r + 8) * HB_STRIDE + col];
                ah[2] = *(const U32*)&hb_hi[r * HB_STRIDE + col + 8];
                ah[3] = *(const U32*)&hb_hi[(r + 8) * HB_STRIDE + col + 8];
                al[0] = *(const U32*)&hb_lo[r * HB_STRIDE + col];
                al[1] = *(const U32*)&hb_lo[(r + 8) * HB_STRIDE + col];
                al[2] = *(const U32*)&hb_lo[r * HB_STRIDE + col + 8];
                al[3] = *(const U32*)&hb_lo[(r + 8) * HB_STRIDE + col + 8];
                int gk = cid * 128 + col;
#pragma unroll
                for (int gate = 0; gate < 3; ++gate) {
                    int nl = gate * 8 + g;
                    U32 bh[2] = {*(const U32*)&Wh[nl * 1032 + gk], *(const U32*)&Wh[nl * 1032 + gk + 8]};
                    U32 bl[2] = {*(const U32*)&Wl[nl * 1032 + gk], *(const U32*)&Wl[nl * 1032 + gk + 8]};
                    mma16816(acc[gate], ah, bh);
                    mma16816(acc[gate], ah, bl);
                    mma16816(acc[gate], al, bh);
                }
            }
        }

        if (ks != 0) {
#pragma unroll
            for (int gate = 0; gate < 3; ++gate)
#pragma unroll
                for (int e = 0; e < 4; ++e) {
                    int rrow = mg * 16 + g + ((e & 2) ? 8 : 0);
                    red[((ks - 1) * 64 + rrow) * 24 + gate * 8 + 2 * t + (e & 1)] = acc[gate][e];
                }
        }
        __syncthreads();
        if (tid == 0) {
            atomicAdd(&g_rdcnt[s], 1);                       // done reading h[s]
            if (s >= 2) while (ldvol(&g_rdcnt[s - 2]) < P2_CTAS) __nanosleep(16);
        }
        __syncthreads();

        if (ks == 0) {
#pragma unroll
            for (int e = 0; e < 4; ++e) {
                int rrow = mg * 16 + g + ((e & 2) ? 8 : 0);
                int jc = 2 * t + (e & 1);
                int j = j0 + jc;
                float ar = acc[0][e], az = acc[1][e], an = acc[2][e];
#pragma unroll
                for (int p = 0; p < 3; ++p) {
                    ar += red[(p * 64 + rrow) * 24 + jc];
                    az += red[(p * 64 + rrow) * 24 + 8 + jc];
                    an += red[(p * 64 + rrow) * 24 + 16 + jc];
                }
                float ir = gi_sm[rrow * 24 + jc];
                float iz = gi_sm[rrow * 24 + 8 + jc];
                float inn = gi_sm[rrow * 24 + 16 + jc];
                float hp = __bfloat162float(hph[rrow * 8 + jc]) + __bfloat162float(hpl[rrow * 8 + jc]);
                float r = 1.f / (1.f + __expf(-(ir + ar)));
                float z = 1.f / (1.f + __expf(-(iz + az)));
                float bn = (e & 1) ? bhn1 : bhn0;
                float n = tanh_fast(inn + r * (an + bn));
                float hn = n + z * (hp - n);
                out[((size_t)s * 64 + rrow) * 1024 + j] = hn;
                if (s + 1 < 512) {
                    float hm = hn * rm_sm[rrow];
                    __nv_bfloat16 h = bhi(hm);
                    g_hhi[nxt][rrow * 1024 + j] = h;
                    g_hlo[nxt][rrow * 1024 + j] = blo(hm, h);
                }
            }
        }
        __threadfence();
        __syncthreads();
        if (tid == 0) atomicAdd(&g_wrcnt[s + 1][grp], 1);    // h[s+1] cols ready
    }
}

extern "C" void kernel_launch(void* const* d_in, const int* in_sizes, int n_in,
                              void* d_out, int out_size) {
    const float*         ins  = (const float*)d_in[0];
    const unsigned char* rs   = (const unsigned char*)d_in[1];
    const float*         Wi   = (const float*)d_in[2];
    const float*         bi   = (const float*)d_in[3];
    const float*         Whm  = (const float*)d_in[4];
    const float*         bhn  = (const float*)d_in[5];
    float*               out  = (float*)d_out;
    (void)in_sizes; (void)n_in; (void)out_size;

    __nv_bfloat16 *whh, *whl, *wih, *wil;
    cudaGetSymbolAddress((void**)&whh, g_whh);
    cudaGetSymbolAddress((void**)&whl, g_whl);
    cudaGetSymbolAddress((void**)&wih, g_wih);
    cudaGetSymbolAddress((void**)&wil, g_wil);

    cudaFuncSetAttribute(phase1, cudaFuncAttributeMaxDynamicSharedMemorySize, 2 * P1_BUF);
    cudaFuncSetAttribute(phase2, cudaFuncAttributeMaxDynamicSharedMemorySize, SM_TOT);

    initk<<<64, 256>>>(rs);
    rmaskk<<<128, 256>>>(rs);
    convA<<<(33554432 + 255) / 256, 256>>>(ins);
    convW<<<(3145728 + 255) / 256, 256>>>(Wi, wih, wil);
    convW<<<(3145728 + 255) / 256, 256>>>(Whm, whh, whl);
    phase1<<<dim3(24, 256), 256, 2 * P1_BUF>>>(bi);
    phase2<<<P2_CTAS, 512, SM_TOT>>>(bhn, out);
}

// round 17
// speedup vs baseline: 1.4165x; 1.0067x over previous
#include <cuda_runtime.h>
#include <cuda_bf16.h>
#include <cstdint>
#include <math.h>

#define DI __device__ __forceinline__
typedef unsigned U32;

// T=512, B=64, H=1024, 3H=3072, M=T*B=32768
__device__ float          g_gi[100663296];        // [32768][3072]
__device__ __nv_bfloat16  g_whh[3145728];         // W_h^T hi [3072][1024]
__device__ __nv_bfloat16  g_whl[3145728];         // W_h^T lo
__device__ __nv_bfloat16  g_wih[3145728];         // W_i^T hi [3072][1024]
__device__ __nv_bfloat16  g_wil[3145728];         // W_i^T lo
__device__ __nv_bfloat16  g_aih[33554432];        // ins hi [32768][1024]
__device__ __nv_bfloat16  g_ail[33554432];        // ins lo
__device__ __nv_bfloat16  g_hhi[3][65536];        // masked h split-bf16 [par3][64][1024]
__device__ __nv_bfloat16  g_hlo[3][65536];
__device__ float          g_rmask[32768];         // [512][64]: reset?0:1
__device__ int            g_wrcnt[513][8];        // producer flags per col-group
__device__ int            g_rdcnt[513];           // consume-done per step
__device__ int            g_rmode;                // 0=int32 1=uint8 2=float32

DI void mma16816(float d[4], const U32 a[4], const U32 b[2]) {
    asm volatile(
        "mma.sync.aligned.m16n8k16.row.col.f32.bf16.bf16.f32 "
        "{%0,%1,%2,%3},{%4,%5,%6,%7},{%8,%9},{%0,%1,%2,%3};\n"
        : "+f"(d[0]), "+f"(d[1]), "+f"(d[2]), "+f"(d[3])
        : "r"(a[0]), "r"(a[1]), "r"(a[2]), "r"(a[3]), "r"(b[0]), "r"(b[1]));
}
DI __nv_bfloat16 bhi(float x) { return __float2bfloat16(x); }
DI __nv_bfloat16 blo(float x, __nv_bfloat16 h) { return __float2bfloat16(x - __bfloat162float(h)); }

DI void cpa16(void* dst, const void* src) {
    unsigned d = (unsigned)__cvta_generic_to_shared(dst);
    asm volatile("cp.async.cg.shared.global [%0], [%1], 16;\n" :: "r"(d), "l"(src));
}
DI void cpcommit() { asm volatile("cp.async.commit_group;\n" ::: "memory"); }
template<int N> DI void cpwait() { asm volatile("cp.async.wait_group %0;\n" :: "n"(N) : "memory"); }
DI float tanh_fast(float x) { float y; asm("tanh.approx.f32 %0, %1;\n" : "=f"(y) : "f"(x)); return y; }
DI int ldvol(const int* p) { return *(volatile const int*)p; }

// -------- init: zero h buffers + flags, probe resets dtype --------
__global__ void initk(const unsigned char* __restrict__ rs) {
    int i = blockIdx.x * blockDim.x + threadIdx.x;
    int nt = gridDim.x * blockDim.x;
    if (i == 0) {
        int mode = 0;
        for (int b = 0; b < 16384; ++b) {
            if ((b & 3) == 3 && rs[b] == 0x3F) { mode = 2; break; }
            if ((b & 3) != 0 && rs[b] != 0 && mode == 0) mode = 1;
        }
        g_rmode = mode;
    }
    for (int k = i; k < 3 * 65536; k += nt) {
        (&g_hhi[0][0])[k] = __float2bfloat16(0.0f);
        (&g_hlo[0][0])[k] = __float2bfloat16(0.0f);
    }
    for (int k = i; k < 513 * 8; k += nt) (&g_wrcnt[0][0])[k] = (k < 8) ? 16 : 0;
    for (int k = i; k < 513; k += nt) g_rdcnt[k] = 0;
}

// -------- resets -> float mask --------
__global__ void rmaskk(const unsigned char* __restrict__ rs) {
    int i = blockIdx.x * blockDim.x + threadIdx.x;
    if (i >= 32768) return;
    int mode = g_rmode;
    int v = (mode == 1) ? rs[i] : (mode == 0) ? rs[i * 4] : rs[i * 4 + 3];
    g_rmask[i] = v ? 0.f : 1.f;
}

// -------- split conversions --------
__global__ void convA(const float* __restrict__ A) {
    int i = blockIdx.x * 256 + threadIdx.x;
    if (i >= 33554432) return;
    float x = A[i];
    __nv_bfloat16 h = bhi(x);
    g_aih[i] = h; g_ail[i] = blo(x, h);
}
__global__ void convW(const float* __restrict__ W, __nv_bfloat16* __restrict__ oh,
                      __nv_bfloat16* __restrict__ ol) {
    int idx = blockIdx.x * 256 + threadIdx.x;
    if (idx >= 3072 * 1024) return;
    int k = idx / 3072, n = idx % 3072;
    float x = W[idx];
    __nv_bfloat16 h = bhi(x);
    oh[(size_t)n * 1024 + k] = h;
    ol[(size_t)n * 1024 + k] = blo(x, h);
}

// -------- phase 1: gi = ins @ W_i + b_i, pre-split bf16, double-buffered ----
#define P1_BUF 40960
__global__ void __launch_bounds__(256, 1)
phase1(const float* __restrict__ bias) {
    extern __shared__ __align__(16) char sm[];
    const int tid = threadIdx.x, warp = tid >> 5, lane = tid & 31;
    const int g = lane >> 2, t = lane & 3;
    const int m0 = blockIdx.y * 128, n0 = blockIdx.x * 128;
    const int wm = (warp & 3) * 32, wn = (warp >> 2) * 64;
    const int row = tid >> 1, half = tid & 1;

    float acc[2][8][4];
#pragma unroll
    for (int mi = 0; mi < 2; ++mi)
#pragma unroll
        for (int ni = 0; ni < 8; ++ni)
#pragma unroll
            for (int e = 0; e < 4; ++e) acc[mi][ni][e] = 0.f;

    auto issue = [&](int buf, int ki) {
        char* b = sm + buf * P1_BUF;
        size_t am = (size_t)(m0 + row) * 1024 + ki;
        size_t bn = (size_t)(n0 + row) * 1024 + ki;
#pragma unroll
        for (int ss = 0; ss < 2; ++ss) {
            int seg = half * 2 + ss;
            cpa16(b + row * 80 + seg * 16,         g_aih + am + seg * 8);
            cpa16(b + 10240 + row * 80 + seg * 16, g_ail + am + seg * 8);
            cpa16(b + 20480 + row * 80 + seg * 16, g_wih + bn + seg * 8);
            cpa16(b + 30720 + row * 80 + seg * 16, g_wil + bn + seg * 8);
        }
    };

    issue(0, 0); cpcommit();
    for (int i = 0; i < 32; ++i) {
        if (i + 1 < 32) { issue((i + 1) & 1, (i + 1) * 32); cpcommit(); }
        if (i + 1 < 32) cpwait<1>(); else cpwait<0>();
        __syncthreads();
        const __nv_bfloat16* Ah = (const __nv_bfloat16*)(sm + (i & 1) * P1_BUF);
        const __nv_bfloat16* Al = Ah + 5120;
        const __nv_bfloat16* Bh = Ah + 10240;
        const __nv_bfloat16* Bl = Ah + 15360;
#pragma unroll
        for (int k16 = 0; k16 < 2; ++k16) {
            int kk = k16 * 16 + 2 * t;
            U32 ah[2][4], al[2][4];
#pragma unroll
            for (int mi = 0; mi < 2; ++mi) {
                int r = wm + mi * 16 + g;
                ah[mi][0] = *(const U32*)&Ah[r * 40 + kk];       ah[mi][1] = *(const U32*)&Ah[(r + 8) * 40 + kk];
                ah[mi][2] = *(const U32*)&Ah[r * 40 + kk + 8];   ah[mi][3] = *(const U32*)&Ah[(r + 8) * 40 + kk + 8];
                al[mi][0] = *(const U32*)&Al[r * 40 + kk];       al[mi][1] = *(const U32*)&Al[(r + 8) * 40 + kk];
                al[mi][2] = *(const U32*)&Al[r * 40 + kk + 8];   al[mi][3] = *(const U32*)&Al[(r + 8) * 40 + kk + 8];
            }
#pragma unroll
            for (int ni = 0; ni < 8; ++ni) {
                int nn = wn + ni * 8 + g;
                U32 bh[2] = {*(const U32*)&Bh[nn * 40 + kk], *(const U32*)&Bh[nn * 40 + kk + 8]};
                U32 bl[2] = {*(const U32*)&Bl[nn * 40 + kk], *(const U32*)&Bl[nn * 40 + kk + 8]};
#pragma unroll
                for (int mi = 0; mi < 2; ++mi) {
                    mma16816(acc[mi][ni], ah[mi], bh);
                    mma16816(acc[mi][ni], ah[mi], bl);
                    mma16816(acc[mi][ni], al[mi], bh);
                }
            }
        }
        __syncthreads();
    }
#pragma unroll
    for (int mi = 0; mi < 2; ++mi)
#pragma unroll
        for (int ni = 0; ni < 8; ++ni)
#pragma unroll
            for (int e = 0; e < 4; ++e) {
                int r2 = m0 + wm + mi * 16 + g + ((e & 2) ? 8 : 0);
                int c2 = n0 + wn + ni * 8 + 2 * t + (e & 1);
                g_gi[(size_t)r2 * 3072 + c2] = acc[mi][ni][e] + bias[c2];
            }
}

// -------- phase 2: persistent recurrence, warp-local flags, parallel epi ----
#define P2_CTAS 128
#define SM_WH   0
#define SM_WL   49536
#define SM_HB   99072
#define HB_STRIDE 136
#define HB_BUF  (2 * 64 * 136)
#define SM_RED  SM_HB                     // red[4][64][24] f32 aliases HB (dead)
#define SM_GI   203520
#define SM_HPH  209664
#define SM_HPL  210688
#define SM_RM   211712
#define SM_BHN  211968
#define SM_TOT  212096

__global__ void __launch_bounds__(512, 1)
phase2(const float* __restrict__ bhn, float* __restrict__ out) {
    extern __shared__ __align__(16) char smraw[];
    __nv_bfloat16* Wh  = (__nv_bfloat16*)(smraw + SM_WH);
    __nv_bfloat16* Wl  = (__nv_bfloat16*)(smraw + SM_WL);
    __nv_bfloat16* HB  = (__nv_bfloat16*)(smraw + SM_HB);
    float* red   = (float*)(smraw + SM_RED);
    float* gi_sm = (float*)(smraw + SM_GI);
    __nv_bfloat16* hph = (__nv_bfloat16*)(smraw + SM_HPH);
    __nv_bfloat16* hpl = (__nv_bfloat16*)(smraw + SM_HPL);
    float* rm_sm = (float*)(smraw + SM_RM);
    float* bhn_sm = (float*)(smraw + SM_BHN);

    const int tid = threadIdx.x, warp = tid >> 5, lane = tid & 31;
    const int g = lane >> 2, t = lane & 3;
    const int j0 = blockIdx.x * 8, grp = blockIdx.x >> 4;
    const int mg = warp & 3, ks = warp >> 2;

    for (int i = tid; i < 3072; i += 512) {         // W_h slice resident
        int nl = i >> 7, o8 = (i & 127) << 3;
        size_t ng = (size_t)((nl >> 3) * 1024 + j0 + (nl & 7)) * 1024 + o8;
        *(uint4*)&Wh[nl * 1032 + o8] = *(const uint4*)&g_whh[ng];
        *(uint4*)&Wl[nl * 1032 + o8] = *(const uint4*)&g_whl[ng];
    }
    if (tid < 8) bhn_sm[tid] = bhn[j0 + tid];
    __syncthreads();

    const int cp_row = tid >> 3, cp_q = tid & 7;
    const int erow = tid >> 3, ejc = tid & 7;       // epilogue element

    for (int s = 0; s < 512; ++s) {
        const int par = s % 3, nxt = (s + 1) % 3;
        const __nv_bfloat16* Ahg = g_hhi[par];
        const __nv_bfloat16* Alg = g_hlo[par];

        auto issue_chunk = [&](int buf, int cid) {
            __nv_bfloat16* dhi = HB + buf * HB_BUF;
            __nv_bfloat16* dlo = dhi + 64 * HB_STRIDE;
            const __nv_bfloat16* shi = Ahg + cp_row * 1024 + cid * 128;
            const __nv_bfloat16* slo = Alg + cp_row * 1024 + cid * 128;
#pragma unroll
            for (int s4 = 0; s4 < 2; ++s4) {
                int seg = cp_q * 2 + s4;
                cpa16(dhi + cp_row * HB_STRIDE + seg * 8, shi + seg * 8);
                cpa16(dlo + cp_row * HB_STRIDE + seg * 8, slo + seg * 8);
            }
        };
        auto waitflag = [&](int cid) {              // warp-local wait
            if (lane == 0)
                while (ldvol(&g_wrcnt[s][cid]) < 16) __nanosleep(16);
            __syncwarp();
        };

        // preload chunks 0,1 (rotated start = own group) + epilogue prefetch
#pragma unroll
        for (int p = 0; p < 2; ++p) {
            int cid = (grp + p) & 7;
            waitflag(cid);
            issue_chunk(p, cid);
            if (p == 0) {
                if (tid < 384) {        // gi slice: 64 rows x 3 gates x 2 halves
                    int rrow = tid / 6, rem = tid % 6, gate = rem >> 1, hf = rem & 1;
                    cpa16(gi_sm + rrow * 24 + gate * 8 + hf * 4,
                          g_gi + ((size_t)s * 64 + rrow) * 3072 + gate * 1024 + j0 + hf * 4);
                } else if (tid < 448) { // h_prev hi (own cols, self-produced)
                    int k = tid - 384;
                    cpa16(hph + k * 8, g_hhi[par] + k * 1024 + j0);
                } else {                // h_prev lo
                    int k = tid - 448;
                    cpa16(hpl + k * 8, g_hlo[par] + k * 1024 + j0);
                }
                if (tid < 16) {         // reset mask for step s+1
                    int sn = (s + 1 < 512) ? s + 1 : 511;
                    cpa16(rm_sm + tid * 4, g_rmask + sn * 64 + tid * 4);
                }
            }
            cpcommit();
        }

        float acc[3][4];
#pragma unroll
        for (int q = 0; q < 3; ++q)
#pragma unroll
            for (int e = 0; e < 4; ++e) acc[q][e] = 0.f;

        for (int c = 0; c < 8; ++c) {
            if (c + 2 < 8) {
                int cid = (grp + c + 2) & 7;
                waitflag(cid);
                issue_chunk((c + 2) % 3, cid);
                cpcommit();
            }
            if (c + 2 < 8) cpwait<2>(); else if (c + 1 < 8) cpwait<1>(); else cpwait<0>();
            __syncthreads();
            const int cid = (grp + c) & 7;
            const __nv_bfloat16* hb_hi = HB + (c % 3) * HB_BUF;
            const __nv_bfloat16* hb_lo = hb_hi + 64 * HB_STRIDE;
#pragma unroll
            for (int k16 = 0; k16 < 2; ++k16) {
                int col = ks * 32 + k16 * 16 + 2 * t;
                int r = mg * 16 + g;
                U32 ah[4], al[4];
                ah[0] = *(const U32*)&hb_hi[r * HB_STRIDE + col];
                ah[1] = *(const U32*)&hb_hi[(r + 8) * HB_STRIDE + col];
                ah[2] = *(const U32*)&hb_hi[r * HB_STRIDE + col + 8];
                ah[3] = *(const U32*)&hb_hi[(r + 8) * HB_STRIDE + col + 8];
                al[0] = *(const U32*)&hb_lo[r * HB_STRIDE + col];
                al[1] = *(const U32*)&hb_lo[(r + 8) * HB_STRIDE + col];
                al[2] = *(const U32*)&hb_lo[r * HB_STRIDE + col + 8];
                al[3] = *(const U32*)&hb_lo[(r + 8) * HB_STRIDE + col + 8];
                int gk = cid * 128 + col;
#pragma unroll
                for (int gate = 0; gate < 3; ++gate) {
                    int nl = gate * 8 + g;
                    U32 bh[2] = {*(const U32*)&Wh[nl * 1032 + gk], *(const U32*)&Wh[nl * 1032 + gk + 8]};
                    U32 bl[2] = {*(const U32*)&Wl[nl * 1032 + gk], *(const U32*)&Wl[nl * 1032 + gk + 8]};
                    mma16816(acc[gate], ah, bh);
                    mma16816(acc[gate], ah, bl);
                    mma16816(acc[gate], al, bh);
                }
            }
        }

        // ---- ALL warps store partials (red aliases dead HB buffers) ----
#pragma unroll
        for (int gate = 0; gate < 3; ++gate)
#pragma unroll
            for (int e = 0; e < 4; ++e) {
                int rrow = mg * 16 + g + ((e & 2) ? 8 : 0);
                red[(ks * 64 + rrow) * 24 + gate * 8 + 2 * t + (e & 1)] = acc[gate][e];
            }
        __syncthreads();
        if (tid == 0) atomicAdd(&g_rdcnt[s], 1);    // all reads of h[s] done

        // ---- epilogue: one element per thread ----
        {
            float ar = 0.f, az = 0.f, an = 0.f;
#pragma unroll
            for (int p = 0; p < 4; ++p) {
                ar += red[(p * 64 + erow) * 24 + ejc];
                az += red[(p * 64 + erow) * 24 + 8 + ejc];
                an += red[(p * 64 + erow) * 24 + 16 + ejc];
            }
            float ir = gi_sm[erow * 24 + ejc];
            float iz = gi_sm[erow * 24 + 8 + ejc];
            float inn = gi_sm[erow * 24 + 16 + ejc];
            float hp = __bfloat162float(hph[erow * 8 + ejc]) + __bfloat162float(hpl[erow * 8 + ejc]);
            float r = 1.f / (1.f + __expf(-(ir + ar)));
            float z = 1.f / (1.f + __expf(-(iz + az)));
            float n = tanh_fast(inn + r * (an + bhn_sm[ejc]));
            float hn = n + z * (hp - n);
            out[((size_t)s * 64 + erow) * 1024 + j0 + ejc] = hn;
            if (s + 1 < 512) {
                float hm = hn * rm_sm[erow];
                __nv_bfloat16 h = bhi(hm);
                if (s >= 2) {                       // guard h[s-2] buffer overwrite
                    if (lane == 0)
                        while (ldvol(&g_rdcnt[s - 2]) < P2_CTAS) __nanosleep(16);
                    __syncwarp();
                }
                g_hhi[nxt][erow * 1024 + j0 + ejc] = h;
                g_hlo[nxt][erow * 1024 + j0 + ejc] = blo(hm, h);
            }
        }
        __threadfence();
        __syncthreads();                            // stores done + red/HB alias guard
        if (tid == 0) atomicAdd(&g_wrcnt[s + 1][grp], 1);
    }
}

extern "C" void kernel_launch(void* const* d_in, const int* in_sizes, int n_in,
                              void* d_out, int out_size) {
    const float*         ins  = (const float*)d_in[0];
    const unsigned char* rs   = (const unsigned char*)d_in[1];
    const float*         Wi   = (const float*)d_in[2];
    const float*         bi   = (const float*)d_in[3];
    const float*         Whm  = (const float*)d_in[4];
    const float*         bhn  = (const float*)d_in[5];
    float*               out  = (float*)d_out;
    (void)in_sizes; (void)n_in; (void)out_size;

    __nv_bfloat16 *whh, *whl, *wih, *wil;
    cudaGetSymbolAddress((void**)&whh, g_whh);
    cudaGetSymbolAddress((void**)&whl, g_whl);
    cudaGetSymbolAddress((void**)&wih, g_wih);
    cudaGetSymbolAddress((void**)&wil, g_wil);

    cudaFuncSetAttribute(phase1, cudaFuncAttributeMaxDynamicSharedMemorySize, 2 * P1_BUF);
    cudaFuncSetAttribute(phase2, cudaFuncAttributeMaxDynamicSharedMemorySize, SM_TOT);

    initk<<<64, 256>>>(rs);
    rmaskk<<<128, 256>>>(rs);
    convA<<<(33554432 + 255) / 256, 256>>>(ins);
    convW<<<(3145728 + 255) / 256, 256>>>(Wi, wih, wil);
    convW<<<(3145728 + 255) / 256, 256>>>(Whm, whh, whl);
    phase1<<<dim3(24, 256), 256, 2 * P1_BUF>>>(bi);
    phase2<<<P2_CTAS, 512, SM_TOT>>>(bhn, out);
}